// round 4
// baseline (speedup 1.0000x reference)
#include <cuda_runtime.h>
#include <cuda_fp16.h>

// Problem constants (from reference): B=256, T_MAX=D_MAX=256, TP=DP=257
#define NTHREADS 512
#define NWARPS   16
#define L_PAD    66049          // 257*257
#define EPS_C    1e-12f

// Shared memory layout (in floats)
#define U_OFF    0              // u[260]
#define V_OFF    260            // v[260]
#define RMAX_OFF 520            // row max [260]
#define CMAX_OFF 780            // col max [260]
#define RED_OFF  1040           // per-warp reduce buffer [16][264]
#define RED_STR  264
#define SVW_OFF  (RED_OFF + NWARPS * RED_STR)   // 5264: per-warp sum(v) partials
#define SUW_OFF  (SVW_OFF + 16)                 // 5280: per-warp sum(u) partials
#define K_OFF    (SUW_OFF + 16)                 // 5296: K matrix storage
#define SMEM_FLOATS 58112                       // 232448 bytes / 4
#define KCAP     (SMEM_FLOATS - K_OFF)          // 52816 fp32 slots for K
#define SMEM_BYTES (SMEM_FLOATS * 4)

// Deterministic 3-way product (must be bit-identical across both argmax passes)
__device__ __forceinline__ float tmul3(float u, float k, float v) {
    return __fmul_rn(__fmul_rn(u, k), v);
}

template<bool F32>
__device__ void run_ex(const float* __restrict__ aff, int nt, int nd,
                       float* __restrict__ oT, float* __restrict__ oA,
                       float* sm)
{
    const int tid  = threadIdx.x;
    const int lane = tid & 31;
    const int w    = tid >> 5;
    const int ndp  = F32 ? ((nd + 3) & ~3) : ((nd + 7) & ~7);  // padded row width

    float*  u_s    = sm + U_OFF;
    float*  v_s    = sm + V_OFF;
    float*  rmax_s = sm + RMAX_OFF;
    float*  cmax_s = sm + CMAX_OFF;
    float*  red    = sm + RED_OFF;
    float*  svw    = sm + SVW_OFF;
    float*  suw    = sm + SUW_OFF;
    float*  Kf     = sm + K_OFF;
    __half* Kh     = (__half*)(sm + K_OFF);

    // Lane column ownership: 8 cols as two quads.
    //  fp32: quad0 = cols [4l..4l+3], quad1 = [128+4l..128+4l+3]  (contiguous LDS.128 per quad)
    //  fp16: cols [8l..8l+7] (one 16B LDS covers both quads)
    const int  cq0 = F32 ? 4 * lane : 8 * lane;
    const int  cq1 = F32 ? 4 * lane + 128 : 8 * lane + 4;
    const bool ok0 = cq0 < ndp;
    const bool ok1 = cq1 < ndp;

    // ---------------- Build K = exp(10*aff) on interior, 0-padded ----------------
    for (int r = w; r < nt; r += NWARPS) {
        const float* arow = aff + (size_t)r * 256;
        if (F32) {
            float* krow = Kf + (size_t)r * ndp;
            if (ok0) {
                float v0[4];
                #pragma unroll
                for (int i = 0; i < 4; i++) { int c = cq0 + i; v0[i] = (c < nd) ? expf(10.0f * arow[c]) : 0.f; }
                *(float4*)(krow + cq0) = make_float4(v0[0], v0[1], v0[2], v0[3]);
            }
            if (ok1) {
                float v1[4];
                #pragma unroll
                for (int i = 0; i < 4; i++) { int c = cq1 + i; v1[i] = (c < nd) ? expf(10.0f * arow[c]) : 0.f; }
                *(float4*)(krow + cq1) = make_float4(v1[0], v1[1], v1[2], v1[3]);
            }
        } else {
            __half* krow = Kh + (size_t)r * ndp;
            if (ok0) {
                #pragma unroll
                for (int i = 0; i < 8; i++) {
                    int c = cq0 + i;
                    krow[c] = __float2half_rn((c < nd) ? expf(10.0f * arow[c]) : 0.f);
                }
            }
        }
    }

    // ---------------- init v0 = col_valid, sum(v0) = nd+1 ----------------
    for (int c = tid; c < 260; c += NTHREADS) v_s[c] = (c <= nd) ? 1.f : 0.f;
    if (tid < NWARPS) { svw[tid] = (tid == 0) ? (float)(nd + 1) : 0.f; suw[tid] = 0.f; }
    __syncthreads();

    auto loadK = [&](int r, float* kr) {
        if (F32) {
            const float* krow = Kf + (size_t)r * ndp;
            if (ok0) { float4 q = *(const float4*)(krow + cq0); kr[0]=q.x; kr[1]=q.y; kr[2]=q.z; kr[3]=q.w; }
            else     { kr[0]=kr[1]=kr[2]=kr[3]=0.f; }
            if (ok1) { float4 q = *(const float4*)(krow + cq1); kr[4]=q.x; kr[5]=q.y; kr[6]=q.z; kr[7]=q.w; }
            else     { kr[4]=kr[5]=kr[6]=kr[7]=0.f; }
        } else {
            if (ok0) {
                const uint4 raw = *(const uint4*)(Kh + (size_t)r * ndp + cq0);
                float2 f;
                f = __half22float2(*(const __half2*)&raw.x); kr[0]=f.x; kr[1]=f.y;
                f = __half22float2(*(const __half2*)&raw.y); kr[2]=f.x; kr[3]=f.y;
                f = __half22float2(*(const __half2*)&raw.z); kr[4]=f.x; kr[5]=f.y;
                f = __half22float2(*(const __half2*)&raw.w); kr[6]=f.x; kr[7]=f.y;
            } else {
                #pragma unroll
                for (int m = 0; m < 8; m++) kr[m] = 0.f;
            }
        }
    };
    auto colOf = [&](int m) { return (m < 4) ? (cq0 + m) : (cq1 + m - 4); };
    auto loadV = [&](float* vr) {
        if (ok0) { float4 q = *(const float4*)(v_s + cq0); vr[0]=q.x; vr[1]=q.y; vr[2]=q.z; vr[3]=q.w; }
        else     { vr[0]=vr[1]=vr[2]=vr[3]=0.f; }
        if (ok1) { float4 q = *(const float4*)(v_s + cq1); vr[4]=q.x; vr[5]=q.y; vr[6]=q.z; vr[7]=q.w; }
        else     { vr[4]=vr[5]=vr[6]=vr[7]=0.f; }
    };

    const float ndf = (float)nd, ntf = (float)nt;

    // ---------------- 100 Sinkhorn iterations, one K sweep each ----------------
    for (int it = 0; it < 100; ++it) {
        // ---- Phase A: rows. u = 1/((Kv)_r + eps); accumulate z += u_r * K_r,:
        float sumv = 0.f;
        #pragma unroll
        for (int k = 0; k < NWARPS; k++) sumv += svw[k];
        const float u_top = ndf / (sumv + EPS_C);   // u[nt] (dummy row: (Kv)_nt = sum(v))
        const float v_dum = v_s[nd];

        float vr[8], zr[8];
        loadV(vr);
        #pragma unroll
        for (int m = 0; m < 8; m++) zr[m] = 0.f;
        float sumu_l = 0.f;

        for (int r = w; r < nt; r += NWARPS) {
            float kr[8];
            loadK(r, kr);
            float dot = 0.f;
            #pragma unroll
            for (int m = 0; m < 8; m++) dot = fmaf(kr[m], vr[m], dot);
            #pragma unroll
            for (int off = 16; off > 0; off >>= 1) dot += __shfl_xor_sync(0xffffffffu, dot, off);
            const float u = 1.0f / (dot + v_dum + EPS_C);   // row_sums=1 for r<nt; K[r][nd]=1
            if (lane == 0) { u_s[r] = u; sumu_l += u; }
            #pragma unroll
            for (int m = 0; m < 8; m++) zr[m] = fmaf(kr[m], u, zr[m]);
        }
        if (lane == 0) suw[w] = sumu_l;
        {
            float* rrow = red + w * RED_STR;
            if (ok0) *(float4*)(rrow + cq0) = make_float4(zr[0], zr[1], zr[2], zr[3]);
            if (ok1) *(float4*)(rrow + cq1) = make_float4(zr[4], zr[5], zr[6], zr[7]);
        }
        __syncthreads();

        // ---- Phase B: cols. v = 1/((K^T u)_c + eps)
        float sumu = u_top;
        #pragma unroll
        for (int k = 0; k < NWARPS; k++) sumu += suw[k];
        const float v_dnew = ntf / (sumu + EPS_C);  // v[nd]: (K^T u)_nd = sum(u)

        float myv = 0.f;
        if (tid < nd) {
            float z = u_top;                         // dummy row contributes u[nt] to every col
            #pragma unroll
            for (int k = 0; k < NWARPS; k++) z += red[k * RED_STR + tid];
            myv = 1.0f / (z + EPS_C);
            v_s[tid] = myv;
        }
        if (tid == 0) { v_s[nd] = v_dnew; u_s[nt] = u_top; }
        float sv = myv + ((tid == 0) ? v_dnew : 0.f);
        #pragma unroll
        for (int off = 16; off > 0; off >>= 1) sv += __shfl_xor_sync(0xffffffffu, sv, off);
        if (lane == 0) svw[w] = sv;
        __syncthreads();
    }

    // ---------------- Epilogue: transport, mutual argmax, births/deaths, flatten ----------------
    const float v_dF = v_s[nd];
    const float u_tF = u_s[nt];
    float vr[8];
    loadV(vr);

    // E1: row max + col max over interior transport
    float cm[8];
    #pragma unroll
    for (int m = 0; m < 8; m++) cm[m] = -1.f;
    for (int r = w; r < nt; r += NWARPS) {
        float kr[8];
        loadK(r, kr);
        const float u = u_s[r];
        float rmx = -1.f;
        #pragma unroll
        for (int m = 0; m < 8; m++) {
            int c = colOf(m);
            if (c < nd) {
                float t = tmul3(u, kr[m], vr[m]);
                rmx = fmaxf(rmx, t);
                cm[m] = fmaxf(cm[m], t);
            }
        }
        #pragma unroll
        for (int off = 16; off > 0; off >>= 1) rmx = fmaxf(rmx, __shfl_xor_sync(0xffffffffu, rmx, off));
        if (lane == 0) rmax_s[r] = rmx;
    }
    {
        float* rrow = red + w * RED_STR;
        if (ok0) *(float4*)(rrow + cq0) = make_float4(cm[0], cm[1], cm[2], cm[3]);
        if (ok1) *(float4*)(rrow + cq1) = make_float4(cm[4], cm[5], cm[6], cm[7]);
    }
    __syncthreads();
    if (tid < nd) {
        float c2 = -1.f;
        #pragma unroll
        for (int k = 0; k < NWARPS; k++) c2 = fmaxf(c2, red[k * RED_STR + tid]);
        cmax_s[tid] = c2;
    }
    __syncthreads();

    // E2: assignment + write outputs
    const int nd1 = nd + 1;
    float ch[8];
    #pragma unroll
    for (int m = 0; m < 8; m++) ch[m] = 0.f;
    for (int r = w; r < nt; r += NWARPS) {
        float kr[8];
        loadK(r, kr);
        const float u   = u_s[r];
        const float rmx = rmax_s[r];
        const size_t rb = (size_t)r * nd1;
        bool any = false;
        #pragma unroll
        for (int m = 0; m < 8; m++) {
            int c = colOf(m);
            if (c < nd) {
                float t = tmul3(u, kr[m], vr[m]);
                bool a = (t == rmx) && (t == cmax_s[c]);
                oT[rb + c] = t;
                oA[rb + c] = a ? 1.f : 0.f;
                if (a) { any = true; ch[m] = 1.f; }
            }
        }
        bool rowhas = __any_sync(0xffffffffu, any);
        if (lane == 0) {                       // deaths column c = nd
            oT[rb + nd] = __fmul_rn(u, v_dF);
            oA[rb + nd] = rowhas ? 0.f : 1.f;
        }
    }
    {
        float* rrow = red + w * RED_STR;
        if (ok0) *(float4*)(rrow + cq0) = make_float4(ch[0], ch[1], ch[2], ch[3]);
        if (ok1) *(float4*)(rrow + cq1) = make_float4(ch[4], ch[5], ch[6], ch[7]);
    }
    __syncthreads();
    if (tid < nd) {                            // births row r = nt
        float c2 = 0.f;
        #pragma unroll
        for (int k = 0; k < NWARPS; k++) c2 = fmaxf(c2, red[k * RED_STR + tid]);
        size_t idx = (size_t)nt * nd1 + tid;
        oT[idx] = __fmul_rn(u_tF, v_s[tid]);
        oA[idx] = (c2 > 0.f) ? 0.f : 1.f;
    }
    if (tid == 0) {                            // corner (nt, nd)
        size_t idx = (size_t)nt * nd1 + nd;
        oT[idx] = __fmul_rn(u_tF, v_dF);
        oA[idx] = 0.f;
    }
    // zero pad tail up to L
    const int length = (nt + 1) * (nd + 1);
    for (int k = length + tid; k < L_PAD; k += NTHREADS) { oT[k] = 0.f; oA[k] = 0.f; }
}

__global__ void __launch_bounds__(NTHREADS, 1)
assoc_kernel(const float* __restrict__ aff, const int* __restrict__ ndet,
             const int* __restrict__ ntrk, float* __restrict__ outT,
             float* __restrict__ outA)
{
    extern __shared__ float sm[];
    const int b  = blockIdx.x;
    const int nd = ndet[b];
    const int nt = ntrk[b];
    const float* affb = aff + (size_t)b * (256 * 256);
    float* oT = outT + (size_t)b * L_PAD;
    float* oA = outA + (size_t)b * L_PAD;
    const int ndp = (nd + 3) & ~3;
    if (nt * ndp <= KCAP) run_ex<true >(affb, nt, nd, oT, oA, sm);
    else                  run_ex<false>(affb, nt, nd, oT, oA, sm);
}

extern "C" void kernel_launch(void* const* d_in, const int* in_sizes, int n_in,
                              void* d_out, int out_size)
{
    const float* aff  = (const float*)d_in[0];
    const int*   ndet = (const int*)d_in[1];
    const int*   ntrk = (const int*)d_in[2];
    const int    Bn   = in_sizes[1];            // one block per example

    float* out  = (float*)d_out;
    float* outA = out + (size_t)(out_size / 2); // [t_flat | a_flat] halves

    cudaFuncSetAttribute(assoc_kernel, cudaFuncAttributeMaxDynamicSharedMemorySize, SMEM_BYTES);
    assoc_kernel<<<Bn, NTHREADS, SMEM_BYTES>>>(aff, ndet, ntrk, out, outA);
}

// round 5
// speedup vs baseline: 1.2050x; 1.2050x over previous
#include <cuda_runtime.h>
#include <cuda_fp16.h>

// B=256, T_MAX=D_MAX=256, TP=DP=257
#define NTHREADS 512
#define L_PAD    66049          // 257*257
#define EPS_C    1e-12f

// Shared layout (floats)
#define U_OFF    0              // u[260]
#define V_OFF    260            // v[260]
#define RMAX_OFF 520            // row max [260]
#define RHAS_OFF 780            // row-has-assignment flags [260]
#define SUP_OFF  1040           // per-warp sum(u) partials [16]
#define SVP_OFF  1056           // per-warp sum(v) partials [16]
#define K_OFF    1072
#define SMEM_FLOATS 58112       // 232448 B / 4
#define KCAP     (SMEM_FLOATS - K_OFF)   // 57040 fp32 slots
#define SMEM_BYTES (SMEM_FLOATS * 4)

// Deterministic 3-way product: must be bit-identical in every pass that
// recomputes transport (row-max pass, col-max pass, write pass).
__device__ __forceinline__ float tmul3(float u, float k, float v) {
    return __fmul_rn(__fmul_rn(u, k), v);
}

template<bool F32>
__device__ void run_ex(const float* __restrict__ aff, int nt, int nd,
                       float* __restrict__ oT, float* __restrict__ oA,
                       float* sm)
{
    const int tid  = threadIdx.x;
    const int lane = tid & 31;
    const int w    = tid >> 5;

    // Row pitch: odd multiple of 4 (fp32) / 8 (fp16) -> conflict-free
    // strided row loads in pass 1.
    int ndp;
    if (F32) { ndp = (nd + 3) & ~3; if (((ndp >> 2) & 1) == 0) ndp += 4; }
    else     { ndp = (nd + 7) & ~7; if (((ndp >> 3) & 1) == 0) ndp += 8; }

    float*  u_s    = sm + U_OFF;
    float*  v_s    = sm + V_OFF;
    float*  rmax_s = sm + RMAX_OFF;
    float*  rhas   = sm + RHAS_OFF;
    float*  sup    = sm + SUP_OFF;
    float*  svp    = sm + SVP_OFF;
    float*  Kf     = sm + K_OFF;
    __half* Kh     = (__half*)(sm + K_OFF);

    // ---- Pre-zero K region (padding must be exactly 0, never garbage) ----
    const int kwords = F32 ? nt * ndp : (nt * ndp) >> 1;   // in floats, mult of 4
    for (int i = tid * 4; i < kwords; i += NTHREADS * 4)
        *(float4*)(Kf + i) = make_float4(0.f, 0.f, 0.f, 0.f);

    // init v0 = 1 on c<=nd; interior partial sum = nd
    for (int c = tid; c < 260; c += NTHREADS) v_s[c] = (c <= nd) ? 1.f : 0.f;
    if (tid < 16) svp[tid] = (tid == 0) ? (float)nd : 0.f;
    __syncthreads();

    // ---- Build K = exp(10*aff) on interior ----
    {
        const int cq0 = F32 ? 4 * lane : 8 * lane;
        const int cq1 = 4 * lane + 128;
        for (int r = w; r < nt; r += 16) {
            const float* arow = aff + (size_t)r * 256;
            if (F32) {
                float* krow = Kf + (size_t)r * ndp;
                if (cq0 < nd) {
                    float x[4];
                    #pragma unroll
                    for (int i = 0; i < 4; i++) { int c = cq0 + i; x[i] = (c < nd) ? __expf(10.0f * arow[c]) : 0.f; }
                    *(float4*)(krow + cq0) = make_float4(x[0], x[1], x[2], x[3]);
                }
                if (cq1 < nd) {
                    float x[4];
                    #pragma unroll
                    for (int i = 0; i < 4; i++) { int c = cq1 + i; x[i] = (c < nd) ? __expf(10.0f * arow[c]) : 0.f; }
                    *(float4*)(krow + cq1) = make_float4(x[0], x[1], x[2], x[3]);
                }
            } else {
                __half* krow = Kh + (size_t)r * ndp;
                if (cq0 < nd) {
                    __half h[8];
                    #pragma unroll
                    for (int i = 0; i < 8; i++) { int c = cq0 + i; h[i] = __float2half_rn((c < nd) ? __expf(10.0f * arow[c]) : 0.f); }
                    *(uint4*)(krow + cq0) = *(uint4*)h;
                }
            }
        }
    }
    __syncthreads();

    const float ndf = (float)nd, ntf = (float)nt;
    const int   nt4 = nt & ~3;
    const int   ndp2 = 2 * ndp, ndp3 = 3 * ndp, ndp4s = 4 * ndp;
    float u_top = 0.f;

    // ================= 100 Sinkhorn iterations, shuffle-free =================
    for (int it = 0; it < 100; ++it) {
        // ---- Pass 1: thread t = row t. u = 1/((Kv)_r + v[nd] + eps) ----
        float sumv = v_s[nd];
        #pragma unroll
        for (int k = 0; k < 16; k++) sumv += svp[k];
        u_top = ndf / (sumv + EPS_C);
        const float v_dum = v_s[nd];

        float u_val = 0.f;
        if (tid < nt) {
            float a0 = 0.f, a1 = 0.f, a2 = 0.f, a3 = 0.f;
            if (F32) {
                const float* krow = Kf + (size_t)tid * ndp;
                #pragma unroll 4
                for (int c = 0; c < ndp; c += 4) {
                    float4 kk = *(const float4*)(krow + c);
                    float4 vv = *(const float4*)(v_s + c);     // warp-uniform broadcast
                    a0 = fmaf(kk.x, vv.x, a0); a1 = fmaf(kk.y, vv.y, a1);
                    a2 = fmaf(kk.z, vv.z, a2); a3 = fmaf(kk.w, vv.w, a3);
                }
            } else {
                const __half* krow = Kh + (size_t)tid * ndp;
                #pragma unroll 2
                for (int c = 0; c < ndp; c += 8) {
                    uint4  raw = *(const uint4*)(krow + c);
                    float4 v0  = *(const float4*)(v_s + c);
                    float4 v1  = *(const float4*)(v_s + c + 4);
                    float2 f;
                    f = __half22float2(*(__half2*)&raw.x); a0 = fmaf(f.x, v0.x, a0); a1 = fmaf(f.y, v0.y, a1);
                    f = __half22float2(*(__half2*)&raw.y); a2 = fmaf(f.x, v0.z, a2); a3 = fmaf(f.y, v0.w, a3);
                    f = __half22float2(*(__half2*)&raw.z); a0 = fmaf(f.x, v1.x, a0); a1 = fmaf(f.y, v1.y, a1);
                    f = __half22float2(*(__half2*)&raw.w); a2 = fmaf(f.x, v1.z, a2); a3 = fmaf(f.y, v1.w, a3);
                }
            }
            float dot = (a0 + a1) + (a2 + a3);
            u_val = 1.0f / (dot + v_dum + EPS_C);
            u_s[tid] = u_val;
        }
        if (tid == 0) u_s[nt] = u_top;
        // one small butterfly per warp for sum(u) (interior only)
        float su = u_val;
        #pragma unroll
        for (int o = 16; o > 0; o >>= 1) su += __shfl_xor_sync(0xffffffffu, su, o);
        if (lane == 0) sup[w] = su;
        __syncthreads();

        // ---- Pass 2: thread t = col t. v = 1/((K^T u)_c + u_top + eps) ----
        float sumu = u_top;
        #pragma unroll
        for (int k = 0; k < 16; k++) sumu += sup[k];
        const float v_dnew = ntf / (sumu + EPS_C);

        float myv = 0.f;
        if (tid < nd) {
            float z0 = 0.f, z1 = 0.f, z2 = 0.f, z3 = 0.f;
            int r = 0;
            if (F32) {
                const float* p = Kf + tid;                     // coalesced column reads
                for (; r < nt4; r += 4) {
                    float4 uu = *(const float4*)(u_s + r);     // broadcast
                    z0 = fmaf(p[0],     uu.x, z0);
                    z1 = fmaf(p[ndp],   uu.y, z1);
                    z2 = fmaf(p[ndp2],  uu.z, z2);
                    z3 = fmaf(p[ndp3],  uu.w, z3);
                    p += ndp4s;
                }
                for (; r < nt; r++) z0 = fmaf(Kf[tid + (size_t)r * ndp], u_s[r], z0);
            } else {
                const __half* p = Kh + tid;
                for (; r < nt4; r += 4) {
                    float4 uu = *(const float4*)(u_s + r);
                    z0 = fmaf(__half2float(p[0]),    uu.x, z0);
                    z1 = fmaf(__half2float(p[ndp]),  uu.y, z1);
                    z2 = fmaf(__half2float(p[ndp2]), uu.z, z2);
                    z3 = fmaf(__half2float(p[ndp3]), uu.w, z3);
                    p += ndp4s;
                }
                for (; r < nt; r++) z0 = fmaf(__half2float(Kh[tid + (size_t)r * ndp]), u_s[r], z0);
            }
            float z = ((z0 + z1) + (z2 + z3)) + u_top;
            myv = 1.0f / (z + EPS_C);
            v_s[tid] = myv;
        }
        if (tid == 0) v_s[nd] = v_dnew;
        float sv = myv;
        #pragma unroll
        for (int o = 16; o > 0; o >>= 1) sv += __shfl_xor_sync(0xffffffffu, sv, o);
        if (lane == 0) svp[w] = sv;
        __syncthreads();
    }

    // ================= Epilogue =================
    const float v_dF = v_s[nd];
    const float u_tF = u_s[nt];
    const int   nd1  = nd + 1;

    // E1: row max (thread per row, no shuffle). All transport values > 0, pads -> 0.
    if (tid < 260) rhas[tid] = 0.f;
    if (tid < nt) {
        const float u = u_s[tid];
        float rmx = 0.f;
        if (F32) {
            const float* krow = Kf + (size_t)tid * ndp;
            #pragma unroll 4
            for (int c = 0; c < ndp; c += 4) {
                float4 kk = *(const float4*)(krow + c);
                float4 vv = *(const float4*)(v_s + c);
                rmx = fmaxf(rmx, tmul3(u, kk.x, vv.x));
                rmx = fmaxf(rmx, tmul3(u, kk.y, vv.y));
                rmx = fmaxf(rmx, tmul3(u, kk.z, vv.z));
                rmx = fmaxf(rmx, tmul3(u, kk.w, vv.w));
            }
        } else {
            const __half* krow = Kh + (size_t)tid * ndp;
            for (int c = 0; c < nd; c++)
                rmx = fmaxf(rmx, tmul3(u, __half2float(krow[c]), v_s[c]));
        }
        rmax_s[tid] = rmx;
    }
    __syncthreads();

    // E2: column threads — col max, then coalesced interior writes + births.
    if (tid < nd) {
        const float vc = v_s[tid];
        float cmx = 0.f;
        if (F32) {
            const float* p = Kf + tid;
            #pragma unroll 4
            for (int r = 0; r < nt; r++) { cmx = fmaxf(cmx, tmul3(u_s[r], p[0], vc)); p += ndp; }
        } else {
            const __half* p = Kh + tid;
            for (int r = 0; r < nt; r++) { cmx = fmaxf(cmx, tmul3(u_s[r], __half2float(p[0]), vc)); p += ndp; }
        }
        bool colhas = false;
        if (F32) {
            const float* p = Kf + tid;
            for (int r = 0; r < nt; r++) {
                float t = tmul3(u_s[r], p[0], vc);
                bool  a = (t == rmax_s[r]) && (t == cmx);
                size_t idx = (size_t)r * nd1 + tid;
                oT[idx] = t; oA[idx] = a ? 1.f : 0.f;
                if (a) { colhas = true; rhas[r] = 1.f; }   // benign race, all write 1
                p += ndp;
            }
        } else {
            const __half* p = Kh + tid;
            for (int r = 0; r < nt; r++) {
                float t = tmul3(u_s[r], __half2float(p[0]), vc);
                bool  a = (t == rmax_s[r]) && (t == cmx);
                size_t idx = (size_t)r * nd1 + tid;
                oT[idx] = t; oA[idx] = a ? 1.f : 0.f;
                if (a) { colhas = true; rhas[r] = 1.f; }
                p += ndp;
            }
        }
        size_t bidx = (size_t)nt * nd1 + tid;           // births row
        oT[bidx] = __fmul_rn(u_tF, vc);
        oA[bidx] = colhas ? 0.f : 1.f;
    }
    __syncthreads();

    if (tid < nt) {                                      // deaths column
        size_t idx = (size_t)tid * nd1 + nd;
        oT[idx] = __fmul_rn(u_s[tid], v_dF);
        oA[idx] = (rhas[tid] > 0.f) ? 0.f : 1.f;
    }
    if (tid == 0) {                                      // corner
        size_t idx = (size_t)nt * nd1 + nd;
        oT[idx] = __fmul_rn(u_tF, v_dF);
        oA[idx] = 0.f;
    }
    const int length = (nt + 1) * nd1;                   // zero pad tail
    for (int k = length + tid; k < L_PAD; k += NTHREADS) { oT[k] = 0.f; oA[k] = 0.f; }
}

__global__ void __launch_bounds__(NTHREADS, 1)
assoc_kernel(const float* __restrict__ aff, const int* __restrict__ ndet,
             const int* __restrict__ ntrk, float* __restrict__ outT,
             float* __restrict__ outA)
{
    extern __shared__ float sm[];
    const int b  = blockIdx.x;
    const int nd = ndet[b];
    const int nt = ntrk[b];
    const float* affb = aff + (size_t)b * (256 * 256);
    float* oT = outT + (size_t)b * L_PAD;
    float* oA = outA + (size_t)b * L_PAD;

    int ndp4 = (nd + 3) & ~3;
    if (((ndp4 >> 2) & 1) == 0) ndp4 += 4;
    if (nt * ndp4 <= KCAP) run_ex<true >(affb, nt, nd, oT, oA, sm);
    else                   run_ex<false>(affb, nt, nd, oT, oA, sm);
}

extern "C" void kernel_launch(void* const* d_in, const int* in_sizes, int n_in,
                              void* d_out, int out_size)
{
    const float* aff  = (const float*)d_in[0];
    const int*   ndet = (const int*)d_in[1];
    const int*   ntrk = (const int*)d_in[2];
    const int    Bn   = in_sizes[1];

    float* out  = (float*)d_out;
    float* outA = out + (size_t)(out_size / 2);   // [t_flat | a_flat]

    cudaFuncSetAttribute(assoc_kernel, cudaFuncAttributeMaxDynamicSharedMemorySize, SMEM_BYTES);
    assoc_kernel<<<Bn, NTHREADS, SMEM_BYTES>>>(aff, ndet, ntrk, out, outA);
}